// round 11
// baseline (speedup 1.0000x reference)
#include <cuda_runtime.h>
#include <cuda_fp16.h>
#include <math.h>

#define NN 50000
#define EE 800000
#define ETOT (EE + NN)
#define DIM 128
#define HH 4
#define CC 32
#define NEG_SLOPE 0.2f

// ---------------- device scratch (no allocations allowed) ----------------
__device__ int     g_count[NN];
__device__ int     g_rowptr[NN + 1];
__device__ int     g_cursor[NN];
__device__ int     g_colidx[ETOT];
__device__ float   g_h[NN * DIM];          // activated layer input, fp32
__device__ __half2 g_hwh[NN * (DIM / 2)];  // transformed features, fp16 gather array
__device__ float   g_asrc[NN * HH];
__device__ float   g_adst[NN * HH];
__device__ float2  g_Wp1[(DIM / 2) * DIM];
__device__ float2  g_Wp2[(DIM / 2) * DIM];
__device__ float2  g_Wp3[(DIM / 2) * CC];

// ---------------- CSR build ----------------
__global__ void k_count(const int* __restrict__ ei) {
    int e = blockIdx.x * blockDim.x + threadIdx.x;
    if (e < EE) atomicAdd(&g_count[ei[EE + e]], 1);
}

// single-block shuffle-based exclusive scan (N=50000); +1 folds in self loop
__global__ void k_scan() {
    __shared__ int wsum[32];
    __shared__ int carry_s;
    int lane = threadIdx.x & 31;
    int wid  = threadIdx.x >> 5;
    if (threadIdx.x == 0) carry_s = 0;
    __syncthreads();
    for (int base = 0; base < NN; base += 1024) {
        int i = base + threadIdx.x;
        int v = (i < NN) ? (g_count[i] + 1) : 0;   // +1 = self loop
        int x = v;
        #pragma unroll
        for (int off = 1; off < 32; off <<= 1) {
            int t = __shfl_up_sync(0xffffffffu, x, off);
            if (lane >= off) x += t;
        }
        if (lane == 31) wsum[wid] = x;
        __syncthreads();
        if (wid == 0) {
            int y = wsum[lane];
            #pragma unroll
            for (int off = 1; off < 32; off <<= 1) {
                int t = __shfl_up_sync(0xffffffffu, y, off);
                if (lane >= off) y += t;
            }
            wsum[lane] = y;
        }
        __syncthreads();
        int wpre = (wid > 0) ? wsum[wid - 1] : 0;
        int excl = carry_s + wpre + x - v;
        if (i < NN) { g_rowptr[i] = excl; g_cursor[i] = excl; }
        int tot = wsum[31];
        __syncthreads();
        if (threadIdx.x == 0) carry_s += tot;
        __syncthreads();
    }
    if (threadIdx.x == 0) g_rowptr[NN] = carry_s;
}

__global__ void k_fill(const int* __restrict__ ei) {
    int e = blockIdx.x * blockDim.x + threadIdx.x;
    if (e < EE) {
        int d = ei[EE + e];
        int pos = atomicAdd(&g_cursor[d], 1);
        g_colidx[pos] = ei[e];
    } else if (e < EE + NN) {
        int i = e - EE;
        int pos = atomicAdd(&g_cursor[i], 1);
        g_colidx[pos] = i;    // self loop
    }
}

// ---------------- pack ALL weight matrices (one launch) ----------------
__global__ void k_packAll(const float* __restrict__ W1, const float* __restrict__ W2,
                          const float* __restrict__ W3) {
    int i = blockIdx.x * blockDim.x + threadIdx.x;
    if (i < (DIM / 2) * DIM) {
        int k2 = i / DIM, j = i - k2 * DIM;
        g_Wp1[i] = make_float2(W1[(2 * k2) * DIM + j], W1[(2 * k2 + 1) * DIM + j]);
        g_Wp2[i] = make_float2(W2[(2 * k2) * DIM + j], W2[(2 * k2 + 1) * DIM + j]);
    } else {
        int t = i - (DIM / 2) * DIM;
        if (t < (DIM / 2) * CC) {
            int k2 = t / CC, j = t - k2 * CC;
            g_Wp3[t] = make_float2(W3[(2 * k2) * CC + j], W3[(2 * k2 + 1) * CC + j]);
        }
    }
}

__device__ __forceinline__ void ffma2(unsigned long long& d,
                                      unsigned long long a, unsigned long long b) {
    asm("fma.rn.f32x2 %0, %1, %2, %0;" : "+l"(d) : "l"(a), "l"(b));
}

// ---------------- GEMM + attention-coefficient reduction ----------------
template <int FIN, int FOUT, int HEADS_T, bool USE_GH>
__global__ void k_gemm(const float* __restrict__ Xin, const float2* __restrict__ Wp,
                       const float* __restrict__ a_s, const float* __restrict__ a_d) {
    const int R = 8;
    const int NC = FOUT / 32;
    __shared__ float4 xs[4][R][FIN / 4];
    int lane = threadIdx.x & 31, wip = threadIdx.x >> 5;
    int base = (blockIdx.x * 4 + wip) * R;
    const float* __restrict__ X = USE_GH ? (const float*)g_h : Xin;

    #pragma unroll
    for (int r = 0; r < R; r++) {
        int row = base + r;
        float4 v = make_float4(0.f, 0.f, 0.f, 0.f);
        if (row < NN) v = reinterpret_cast<const float4*>(X + (size_t)row * FIN)[lane];
        xs[wip][r][lane] = v;
    }
    __syncwarp();

    unsigned long long acc[R][NC];
    #pragma unroll
    for (int r = 0; r < R; r++)
        #pragma unroll
        for (int c = 0; c < NC; c++) acc[r][c] = 0ull;

    #pragma unroll 4
    for (int k4 = 0; k4 < FIN / 4; k4++) {
        unsigned long long wA[NC], wB[NC];
        #pragma unroll
        for (int c = 0; c < NC; c++) {
            wA[c] = *reinterpret_cast<const unsigned long long*>(
                        &Wp[(2 * k4) * FOUT + c * 32 + lane]);
            wB[c] = *reinterpret_cast<const unsigned long long*>(
                        &Wp[(2 * k4 + 1) * FOUT + c * 32 + lane]);
        }
        #pragma unroll
        for (int r = 0; r < R; r++) {
            ulonglong2 xv = reinterpret_cast<const ulonglong2*>(&xs[wip][r][0])[k4];
            #pragma unroll
            for (int c = 0; c < NC; c++) {
                ffma2(acc[r][c], wA[c], xv.x);
                ffma2(acc[r][c], wB[c], xv.y);
            }
        }
    }

    float asv[NC], adv[NC];
    #pragma unroll
    for (int c = 0; c < NC; c++) {
        asv[c] = a_s[c * 32 + lane];
        adv[c] = a_d[c * 32 + lane];
    }

    __half* __restrict__ hw16 = reinterpret_cast<__half*>(g_hwh);
    #pragma unroll
    for (int r = 0; r < R; r++) {
        int row = base + r;
        #pragma unroll
        for (int c = 0; c < NC; c++) {
            unsigned long long a = acc[r][c];
            float h = __uint_as_float((unsigned)(a & 0xffffffffull)) +
                      __uint_as_float((unsigned)(a >> 32));
            if (row < NN) hw16[(size_t)row * FOUT + c * 32 + lane] = __float2half_rn(h);
            float vs = h * asv[c], vd = h * adv[c];
            #pragma unroll
            for (int off = 16; off; off >>= 1) {
                vs += __shfl_xor_sync(0xffffffffu, vs, off);
                vd += __shfl_xor_sync(0xffffffffu, vd, off);
            }
            if (lane == 0 && row < NN) {
                g_asrc[row * HEADS_T + c] = vs;
                g_adst[row * HEADS_T + c] = vd;
            }
        }
    }
}

// ---------------- layers 1&2: TWO warps per dst, ALL 4 heads ----------------
// Each warp handles alternating 8-edge chunks (halves serial chunk chain);
// partials combined in smem. Lane layout per warp unchanged: parallel phase
// lane = edgeSlot*4 + head; serial phase lane owns 4 channels (head = lane>>3).
// No-max softmax: logits bounded (~|l|<6) by input scaling.
__global__ void k_agg4(const float* __restrict__ bias) {
    __shared__ float4 sacc[4][32];
    __shared__ float  ssum_s[4][4];
    int lane = threadIdx.x & 31;
    int pair = threadIdx.x >> 6;          // dst slot in block (0..3)
    int half = (threadIdx.x >> 5) & 1;    // which warp of the pair
    int dst = blockIdx.x * 4 + pair;      // NN divisible by 4

    int sub = lane & 3;
    int ej  = lane >> 2;
    int myhead = lane >> 3;

    float adv = g_adst[dst * HH + sub];
    int p0 = g_rowptr[dst], p1 = g_rowptr[dst + 1];

    float4 acc = make_float4(0.f, 0.f, 0.f, 0.f);
    float ssum = 0.f;
    const __half2* __restrict__ hp = g_hwh;

    for (int b = p0 + half * 8; b < p1; b += 16) {
        int p = b + ej;
        bool valid = (p < p1);
        int src = g_colidx[valid ? p : (p1 - 1)];
        float t = g_asrc[src * HH + sub] + adv;
        t = (t >= 0.f) ? t : NEG_SLOPE * t;
        float e = valid ? __expf(t) : 0.f;
        int offs = src * (DIM / 2);
        ssum += e;

        float w[8]; int o[8];
        #pragma unroll
        for (int j = 0; j < 8; j++) {
            w[j] = __shfl_sync(0xffffffffu, e, j * 4 + myhead);
            o[j] = __shfl_sync(0xffffffffu, offs, j * 4);
        }
        #pragma unroll
        for (int j = 0; j < 8; j++) {
            uint2 raw = *reinterpret_cast<const uint2*>(hp + o[j] + lane * 2);
            float2 f0 = __half22float2(*reinterpret_cast<__half2*>(&raw.x));
            float2 f1 = __half22float2(*reinterpret_cast<__half2*>(&raw.y));
            acc.x += w[j] * f0.x; acc.y += w[j] * f0.y;
            acc.z += w[j] * f1.x; acc.w += w[j] * f1.y;
        }
    }
    // reduce ssum over edge slots -> every lane holds total for its own sub
    ssum += __shfl_xor_sync(0xffffffffu, ssum, 4);
    ssum += __shfl_xor_sync(0xffffffffu, ssum, 8);
    ssum += __shfl_xor_sync(0xffffffffu, ssum, 16);

    if (half == 1) {
        sacc[pair][lane] = acc;
        if (lane < 4) ssum_s[pair][lane] = ssum;   // lane l holds head-l total
    }
    __syncthreads();
    if (half == 0) {
        float4 pa = sacc[pair][lane];
        acc.x += pa.x; acc.y += pa.y; acc.z += pa.z; acc.w += pa.w;
        float s = __shfl_sync(0xffffffffu, ssum, myhead) + ssum_s[pair][myhead];
        float inv = 1.f / (s + 1e-16f);

        float4 bb = *reinterpret_cast<const float4*>(bias + lane * 4);
        float4 o4;
        o4.x = acc.x * inv + bb.x;
        o4.y = acc.y * inv + bb.y;
        o4.z = acc.z * inv + bb.z;
        o4.w = acc.w * inv + bb.w;
        o4.x = (o4.x > 0.f) ? o4.x : expm1f(o4.x);   // ELU
        o4.y = (o4.y > 0.f) ? o4.y : expm1f(o4.y);
        o4.z = (o4.z > 0.f) ? o4.z : expm1f(o4.z);
        o4.w = (o4.w > 0.f) ? o4.w : expm1f(o4.w);
        *reinterpret_cast<float4*>(g_h + dst * DIM + lane * 4) = o4;
    }
}

// ---------------- layer 3: warp per dst, single head, write out ----------
__global__ void k_agg1(const float* __restrict__ bias, float* __restrict__ OUT) {
    int wip = threadIdx.x >> 5, lane = threadIdx.x & 31;
    int dst = blockIdx.x * 8 + wip;
    if (dst >= NN) return;

    float adv = g_adst[dst];
    int p0 = g_rowptr[dst], p1 = g_rowptr[dst + 1];
    const __half* __restrict__ hw16 = reinterpret_cast<const __half*>(g_hwh);

    float ssum = 0.f;
    float acc = 0.f;
    for (int b = p0; b < p1; b += 32) {
        int p = b + lane;
        bool valid = (p < p1);
        int src = g_colidx[valid ? p : (p1 - 1)];
        float t = g_asrc[src] + adv;
        t = (t >= 0.f) ? t : NEG_SLOPE * t;
        float e = valid ? __expf(t) : 0.f;
        int offs = src * CC;
        ssum += e;

        int cnt = min(32, p1 - b);
        #pragma unroll
        for (int g = 0; g < 4; g++) {
            if (g * 8 >= cnt) break;            // uniform across warp
            float w[8]; int o[8];
            #pragma unroll
            for (int j = 0; j < 8; j++) {
                w[j] = __shfl_sync(0xffffffffu, e, g * 8 + j);
                o[j] = __shfl_sync(0xffffffffu, offs, g * 8 + j);
            }
            #pragma unroll
            for (int j = 0; j < 8; j++)
                acc += w[j] * __half2float(hw16[o[j] + lane]);
        }
    }
    float s = ssum;
    #pragma unroll
    for (int off = 16; off; off >>= 1)
        s += __shfl_xor_sync(0xffffffffu, s, off);

    OUT[dst * CC + lane] = acc / (s + 1e-16f) + bias[lane];
}

// ---------------- launch ----------------
extern "C" void kernel_launch(void* const* d_in, const int* in_sizes, int n_in,
                              void* d_out, int out_size) {
    const float* x   = (const float*)d_in[0];
    const int*   ei  = (const int*)  d_in[1];
    const float* W1  = (const float*)d_in[2];
    const float* as1 = (const float*)d_in[3];
    const float* ad1 = (const float*)d_in[4];
    const float* b1  = (const float*)d_in[5];
    const float* W2  = (const float*)d_in[6];
    const float* as2 = (const float*)d_in[7];
    const float* ad2 = (const float*)d_in[8];
    const float* b2  = (const float*)d_in[9];
    const float* W3  = (const float*)d_in[10];
    const float* as3 = (const float*)d_in[11];
    const float* ad3 = (const float*)d_in[12];
    const float* b3  = (const float*)d_in[13];
    float* out = (float*)d_out;

    static bool init = false;
    static cudaStream_t s2;
    static cudaEvent_t evA, evB;
    static void* cnt_ptr;
    static float2 *wp1, *wp2, *wp3;
    if (!init) {
        cudaStreamCreateWithFlags(&s2, cudaStreamNonBlocking);
        cudaEventCreateWithFlags(&evA, cudaEventDisableTiming);
        cudaEventCreateWithFlags(&evB, cudaEventDisableTiming);
        cudaGetSymbolAddress(&cnt_ptr, g_count);
        cudaGetSymbolAddress((void**)&wp1, g_Wp1);
        cudaGetSymbolAddress((void**)&wp2, g_Wp2);
        cudaGetSymbolAddress((void**)&wp3, g_Wp3);
        init = true;
    }

    // ---- fork: CSR build on s2, pack+gemm1 on main ----
    cudaEventRecord(evA, 0);
    cudaStreamWaitEvent(s2, evA, 0);

    cudaMemsetAsync(cnt_ptr, 0, NN * sizeof(int), s2);
    k_count<<<(EE + 255) / 256, 256, 0, s2>>>(ei);
    k_scan<<<1, 1024, 0, s2>>>();
    k_fill<<<(ETOT + 255) / 256, 256, 0, s2>>>(ei);
    cudaEventRecord(evB, s2);

    const int gemm_blocks = (NN + 31) / 32;
    const int agg4_blocks = NN / 4;           // 2 warps per dst, 4 dst per block
    const int agg1_blocks = (NN + 7) / 8;
    const int pack_blocks = ((DIM / 2) * DIM + (DIM / 2) * CC + 255) / 256;

    k_packAll<<<pack_blocks, 256>>>(W1, W2, W3);
    k_gemm<DIM, DIM, HH, false><<<gemm_blocks, 128>>>(x, wp1, as1, ad1);

    // ---- join: aggregation needs CSR ----
    cudaStreamWaitEvent(0, evB, 0);

    k_agg4<<<agg4_blocks, 256>>>(b1);

    k_gemm<DIM, DIM, HH, true><<<gemm_blocks, 128>>>(nullptr, wp2, as2, ad2);
    k_agg4<<<agg4_blocks, 256>>>(b2);

    k_gemm<DIM, CC, 1, true><<<gemm_blocks, 128>>>(nullptr, wp3, as3, ad3);
    k_agg1<<<agg1_blocks, 256>>>(b3, out);
}

// round 13
// speedup vs baseline: 1.0885x; 1.0885x over previous
#include <cuda_runtime.h>
#include <cuda_fp16.h>
#include <math.h>

#define NN 50000
#define EE 800000
#define ETOT (EE + NN)
#define DIM 128
#define HH 4
#define CC 32
#define NEG_SLOPE 0.2f

// ---------------- device scratch (no allocations allowed) ----------------
__device__ int     g_count[NN];
__device__ int     g_rowptr[NN + 1];
__device__ int     g_cursor[NN];
__device__ int     g_colidx[ETOT];
__device__ float   g_h[NN * DIM];          // activated layer input, fp32
__device__ __half2 g_hwh[NN * (DIM / 2)];  // transformed features, fp16 gather array
__device__ float   g_asrc[NN * HH];
__device__ float   g_adst[NN * HH];
__device__ float2  g_Wp1[(DIM / 2) * DIM];
__device__ float2  g_Wp2[(DIM / 2) * DIM];
__device__ float2  g_Wp3[(DIM / 2) * CC];

// ---------------- CSR build ----------------
__global__ void k_count(const int* __restrict__ ei) {
    int e = blockIdx.x * blockDim.x + threadIdx.x;
    if (e < EE) atomicAdd(&g_count[ei[EE + e]], 1);
}

// single-block shuffle-based exclusive scan (N=50000); +1 folds in self loop
__global__ void k_scan() {
    __shared__ int wsum[32];
    __shared__ int carry_s;
    int lane = threadIdx.x & 31;
    int wid  = threadIdx.x >> 5;
    if (threadIdx.x == 0) carry_s = 0;
    __syncthreads();
    for (int base = 0; base < NN; base += 1024) {
        int i = base + threadIdx.x;
        int v = (i < NN) ? (g_count[i] + 1) : 0;   // +1 = self loop
        int x = v;
        #pragma unroll
        for (int off = 1; off < 32; off <<= 1) {
            int t = __shfl_up_sync(0xffffffffu, x, off);
            if (lane >= off) x += t;
        }
        if (lane == 31) wsum[wid] = x;
        __syncthreads();
        if (wid == 0) {
            int y = wsum[lane];
            #pragma unroll
            for (int off = 1; off < 32; off <<= 1) {
                int t = __shfl_up_sync(0xffffffffu, y, off);
                if (lane >= off) y += t;
            }
            wsum[lane] = y;
        }
        __syncthreads();
        int wpre = (wid > 0) ? wsum[wid - 1] : 0;
        int excl = carry_s + wpre + x - v;
        if (i < NN) { g_rowptr[i] = excl; g_cursor[i] = excl; }
        int tot = wsum[31];
        __syncthreads();
        if (threadIdx.x == 0) carry_s += tot;
        __syncthreads();
    }
    if (threadIdx.x == 0) g_rowptr[NN] = carry_s;
}

__global__ void k_fill(const int* __restrict__ ei) {
    int e = blockIdx.x * blockDim.x + threadIdx.x;
    if (e < EE) {
        int d = ei[EE + e];
        int pos = atomicAdd(&g_cursor[d], 1);
        g_colidx[pos] = ei[e];
    } else if (e < EE + NN) {
        int i = e - EE;
        int pos = atomicAdd(&g_cursor[i], 1);
        g_colidx[pos] = i;    // self loop
    }
}

// ---------------- pack ALL weight matrices (one launch) ----------------
__global__ void k_packAll(const float* __restrict__ W1, const float* __restrict__ W2,
                          const float* __restrict__ W3) {
    int i = blockIdx.x * blockDim.x + threadIdx.x;
    if (i < (DIM / 2) * DIM) {
        int k2 = i / DIM, j = i - k2 * DIM;
        g_Wp1[i] = make_float2(W1[(2 * k2) * DIM + j], W1[(2 * k2 + 1) * DIM + j]);
        g_Wp2[i] = make_float2(W2[(2 * k2) * DIM + j], W2[(2 * k2 + 1) * DIM + j]);
    } else {
        int t = i - (DIM / 2) * DIM;
        if (t < (DIM / 2) * CC) {
            int k2 = t / CC, j = t - k2 * CC;
            g_Wp3[t] = make_float2(W3[(2 * k2) * CC + j], W3[(2 * k2 + 1) * CC + j]);
        }
    }
}

__device__ __forceinline__ void ffma2(unsigned long long& d,
                                      unsigned long long a, unsigned long long b) {
    asm("fma.rn.f32x2 %0, %1, %2, %0;" : "+l"(d) : "l"(a), "l"(b));
}

// ---------------- GEMM + attention-coefficient reduction ----------------
// fp32 math; h stored to g_hwh as fp16 (gather array), logits stay fp32.
template <int FIN, int FOUT, int HEADS_T, bool USE_GH>
__global__ void k_gemm(const float* __restrict__ Xin, const float2* __restrict__ Wp,
                       const float* __restrict__ a_s, const float* __restrict__ a_d) {
    const int R = 8;
    const int NC = FOUT / 32;
    __shared__ float4 xs[4][R][FIN / 4];
    int lane = threadIdx.x & 31, wip = threadIdx.x >> 5;
    int base = (blockIdx.x * 4 + wip) * R;
    const float* __restrict__ X = USE_GH ? (const float*)g_h : Xin;

    #pragma unroll
    for (int r = 0; r < R; r++) {
        int row = base + r;
        float4 v = make_float4(0.f, 0.f, 0.f, 0.f);
        if (row < NN) v = reinterpret_cast<const float4*>(X + (size_t)row * FIN)[lane];
        xs[wip][r][lane] = v;
    }
    __syncwarp();

    unsigned long long acc[R][NC];
    #pragma unroll
    for (int r = 0; r < R; r++)
        #pragma unroll
        for (int c = 0; c < NC; c++) acc[r][c] = 0ull;

    #pragma unroll 4
    for (int k4 = 0; k4 < FIN / 4; k4++) {
        unsigned long long wA[NC], wB[NC];
        #pragma unroll
        for (int c = 0; c < NC; c++) {
            wA[c] = *reinterpret_cast<const unsigned long long*>(
                        &Wp[(2 * k4) * FOUT + c * 32 + lane]);
            wB[c] = *reinterpret_cast<const unsigned long long*>(
                        &Wp[(2 * k4 + 1) * FOUT + c * 32 + lane]);
        }
        #pragma unroll
        for (int r = 0; r < R; r++) {
            ulonglong2 xv = reinterpret_cast<const ulonglong2*>(&xs[wip][r][0])[k4];
            #pragma unroll
            for (int c = 0; c < NC; c++) {
                ffma2(acc[r][c], wA[c], xv.x);
                ffma2(acc[r][c], wB[c], xv.y);
            }
        }
    }

    float asv[NC], adv[NC];
    #pragma unroll
    for (int c = 0; c < NC; c++) {
        asv[c] = a_s[c * 32 + lane];
        adv[c] = a_d[c * 32 + lane];
    }

    __half* __restrict__ hw16 = reinterpret_cast<__half*>(g_hwh);
    #pragma unroll
    for (int r = 0; r < R; r++) {
        int row = base + r;
        #pragma unroll
        for (int c = 0; c < NC; c++) {
            unsigned long long a = acc[r][c];
            float h = __uint_as_float((unsigned)(a & 0xffffffffull)) +
                      __uint_as_float((unsigned)(a >> 32));
            if (row < NN) hw16[(size_t)row * FOUT + c * 32 + lane] = __float2half_rn(h);
            float vs = h * asv[c], vd = h * adv[c];
            #pragma unroll
            for (int off = 16; off; off >>= 1) {
                vs += __shfl_xor_sync(0xffffffffu, vs, off);
                vd += __shfl_xor_sync(0xffffffffu, vd, off);
            }
            if (lane == 0 && row < NN) {
                g_asrc[row * HEADS_T + c] = vs;
                g_adst[row * HEADS_T + c] = vd;
            }
        }
    }
}

// ---------------- layers 1&2: one warp per dst, ALL 4 heads ----------------
// Parallel phase: lane = edgeSlot*4 + head (8 edges/chunk). Serial phase:
// shuffle-broadcast (weight, row offset); fixed 8-iter body, LDG.64 fp16
// gathers (256B per edge row across the warp). Invalid tail edges: weight 0,
// source clamped. No-max softmax: logits bounded (~|l|<6) by input scaling.
__global__ void k_agg4(const float* __restrict__ bias) {
    int wip = threadIdx.x >> 5, lane = threadIdx.x & 31;
    int dst = blockIdx.x * 8 + wip;
    if (dst >= NN) return;

    int sub = lane & 3;          // head in parallel phase
    int ej  = lane >> 2;         // edge slot (0..7)
    int myhead = lane >> 3;      // head owning this lane's 4 channels

    float adv = g_adst[dst * HH + sub];
    int p0 = g_rowptr[dst], p1 = g_rowptr[dst + 1];

    float4 acc = make_float4(0.f, 0.f, 0.f, 0.f);
    float ssum = 0.f;
    const __half2* __restrict__ hp = g_hwh;

    for (int b = p0; b < p1; b += 8) {
        int p = b + ej;
        bool valid = (p < p1);
        int src = g_colidx[valid ? p : (p1 - 1)];   // clamp: always a real row
        float t = g_asrc[src * HH + sub] + adv;
        t = (t >= 0.f) ? t : NEG_SLOPE * t;
        float e = valid ? __expf(t) : 0.f;
        int offs = src * (DIM / 2);                 // half2 units
        ssum += e;

        float w[8]; int o[8];
        #pragma unroll
        for (int j = 0; j < 8; j++) {
            w[j] = __shfl_sync(0xffffffffu, e, j * 4 + myhead);
            o[j] = __shfl_sync(0xffffffffu, offs, j * 4);
        }
        #pragma unroll
        for (int j = 0; j < 8; j++) {
            uint2 raw = *reinterpret_cast<const uint2*>(hp + o[j] + lane * 2);
            float2 f0 = __half22float2(*reinterpret_cast<__half2*>(&raw.x));
            float2 f1 = __half22float2(*reinterpret_cast<__half2*>(&raw.y));
            acc.x += w[j] * f0.x; acc.y += w[j] * f0.y;
            acc.z += w[j] * f1.x; acc.w += w[j] * f1.y;
        }
    }
    // ssum per (ej,sub) -> reduce over edge slots (lane bits 2..4)
    ssum += __shfl_xor_sync(0xffffffffu, ssum, 4);
    ssum += __shfl_xor_sync(0xffffffffu, ssum, 8);
    ssum += __shfl_xor_sync(0xffffffffu, ssum, 16);
    float s = __shfl_sync(0xffffffffu, ssum, myhead);
    float inv = 1.f / (s + 1e-16f);

    float4 bb = *reinterpret_cast<const float4*>(bias + lane * 4);
    float4 o4;
    o4.x = acc.x * inv + bb.x;
    o4.y = acc.y * inv + bb.y;
    o4.z = acc.z * inv + bb.z;
    o4.w = acc.w * inv + bb.w;
    o4.x = (o4.x > 0.f) ? o4.x : expm1f(o4.x);   // ELU
    o4.y = (o4.y > 0.f) ? o4.y : expm1f(o4.y);
    o4.z = (o4.z > 0.f) ? o4.z : expm1f(o4.z);
    o4.w = (o4.w > 0.f) ? o4.w : expm1f(o4.w);
    *reinterpret_cast<float4*>(g_h + dst * DIM + lane * 4) = o4;
}

// ---------------- layer 3: warp per dst, single head, write out ----------
__global__ void k_agg1(const float* __restrict__ bias, float* __restrict__ OUT) {
    int wip = threadIdx.x >> 5, lane = threadIdx.x & 31;
    int dst = blockIdx.x * 8 + wip;
    if (dst >= NN) return;

    float adv = g_adst[dst];
    int p0 = g_rowptr[dst], p1 = g_rowptr[dst + 1];
    const __half* __restrict__ hw16 = reinterpret_cast<const __half*>(g_hwh);

    float ssum = 0.f;
    float acc = 0.f;
    for (int b = p0; b < p1; b += 32) {
        int p = b + lane;
        bool valid = (p < p1);
        int src = g_colidx[valid ? p : (p1 - 1)];
        float t = g_asrc[src] + adv;
        t = (t >= 0.f) ? t : NEG_SLOPE * t;
        float e = valid ? __expf(t) : 0.f;
        int offs = src * CC;
        ssum += e;

        int cnt = min(32, p1 - b);
        #pragma unroll
        for (int g = 0; g < 4; g++) {
            if (g * 8 >= cnt) break;            // uniform across warp
            float w[8]; int o[8];
            #pragma unroll
            for (int j = 0; j < 8; j++) {
                w[j] = __shfl_sync(0xffffffffu, e, g * 8 + j);
                o[j] = __shfl_sync(0xffffffffu, offs, g * 8 + j);
            }
            #pragma unroll
            for (int j = 0; j < 8; j++)
                acc += w[j] * __half2float(hw16[o[j] + lane]);
        }
    }
    float s = ssum;
    #pragma unroll
    for (int off = 16; off; off >>= 1)
        s += __shfl_xor_sync(0xffffffffu, s, off);

    OUT[dst * CC + lane] = acc / (s + 1e-16f) + bias[lane];
}

// ---------------- launch ----------------
extern "C" void kernel_launch(void* const* d_in, const int* in_sizes, int n_in,
                              void* d_out, int out_size) {
    const float* x   = (const float*)d_in[0];
    const int*   ei  = (const int*)  d_in[1];
    const float* W1  = (const float*)d_in[2];
    const float* as1 = (const float*)d_in[3];
    const float* ad1 = (const float*)d_in[4];
    const float* b1  = (const float*)d_in[5];
    const float* W2  = (const float*)d_in[6];
    const float* as2 = (const float*)d_in[7];
    const float* ad2 = (const float*)d_in[8];
    const float* b2  = (const float*)d_in[9];
    const float* W3  = (const float*)d_in[10];
    const float* as3 = (const float*)d_in[11];
    const float* ad3 = (const float*)d_in[12];
    const float* b3  = (const float*)d_in[13];
    float* out = (float*)d_out;

    static bool init = false;
    static void* cnt_ptr;
    static float2 *wp1, *wp2, *wp3;
    if (!init) {
        cudaGetSymbolAddress(&cnt_ptr, g_count);
        cudaGetSymbolAddress((void**)&wp1, g_Wp1);
        cudaGetSymbolAddress((void**)&wp2, g_Wp2);
        cudaGetSymbolAddress((void**)&wp3, g_Wp3);
        init = true;
    }

    // CSR by destination (self-loops folded into scan)
    cudaMemsetAsync(cnt_ptr, 0, NN * sizeof(int));
    k_count<<<(EE + 255) / 256, 256>>>(ei);
    k_scan<<<1, 1024>>>();
    k_fill<<<(ETOT + 255) / 256, 256>>>(ei);

    const int gemm_blocks = (NN + 31) / 32;
    const int agg_blocks = (NN + 7) / 8;
    const int pack_blocks = ((DIM / 2) * DIM + (DIM / 2) * CC + 255) / 256;

    k_packAll<<<pack_blocks, 256>>>(W1, W2, W3);

    // layer 1
    k_gemm<DIM, DIM, HH, false><<<gemm_blocks, 128>>>(x, wp1, as1, ad1);
    k_agg4<<<agg_blocks, 256>>>(b1);

    // layer 2
    k_gemm<DIM, DIM, HH, true><<<gemm_blocks, 128>>>(nullptr, wp2, as2, ad2);
    k_agg4<<<agg_blocks, 256>>>(b2);

    // layer 3
    k_gemm<DIM, CC, 1, true><<<gemm_blocks, 128>>>(nullptr, wp3, as3, ad3);
    k_agg1<<<agg_blocks, 256>>>(b3, out);
}